// round 5
// baseline (speedup 1.0000x reference)
#include <cuda_runtime.h>
#include <cstdint>

#define DIMS   256
#define BATCH  2048
#define NPAIR  32896              // 256*257/2 upper-triangle pairs
#define NROWS  33280              // 260 tiles * 128 rows (pairs + c2 + c1 + pad)
#define BM     128
#define BN     128
#define KC     32
#define NCHUNK (DIMS / KC)        // 8
#define STAGES 3

// ---- device scratch (allocation-free) ----
__device__ float    g_c3p[NROWS * DIMS];         // 34 MB packed+symmetrized A (tf32-rounded)
__device__ uint32_t g_pairIdx[NROWS];            // (i<<16)|j per row
__device__ float    g_rel[BATCH * DIMS];         // rel row-major [b][k]     (tf32-rounded)
__device__ float    g_relT[(DIMS + 1) * BATCH];  // rel^T [k][b] exact; row 256 = 1.0

static __device__ __forceinline__ float f2tf32f(float f) {
    uint32_t r;
    asm("cvt.rna.tf32.f32 %0, %1;" : "=r"(r) : "f"(f));
    return __uint_as_float(r);
}

#define MMA_TF32(C, A0, A1, A2, A3, B0, B1)                                   \
    asm volatile(                                                             \
        "mma.sync.aligned.m16n8k8.row.col.f32.tf32.tf32.f32 "                 \
        "{%0,%1,%2,%3}, {%4,%5,%6,%7}, {%8,%9}, {%0,%1,%2,%3};"               \
        : "+f"((C)[0]), "+f"((C)[1]), "+f"((C)[2]), "+f"((C)[3])              \
        : "r"(A0), "r"(A1), "r"(A2), "r"(A3), "r"(B0), "r"(B1))

#define LDSM4(R, addr)                                                        \
    asm volatile("ldmatrix.sync.aligned.m8n8.x4.shared.b16 {%0,%1,%2,%3}, [%4];" \
        : "=r"((R)[0]), "=r"((R)[1]), "=r"((R)[2]), "=r"((R)[3])              \
        : "r"(addr))

static __device__ __forceinline__ void cp16(uint32_t dst, uint64_t gsrc) {
    asm volatile("cp.async.cg.shared.global [%0], [%1], 16;"
                 :: "r"(dst), "l"(gsrc) : "memory");
}
#define CP_COMMIT() asm volatile("cp.async.commit_group;" ::: "memory")
#define CP_WAIT2()  asm volatile("cp.async.wait_group 2;" ::: "memory")

static __device__ __forceinline__ uint32_t smem_u32(const void* p) {
    uint32_t a;
    asm("{ .reg .u64 t; cvta.to.shared.u64 t, %1; cvt.u32.u64 %0, t; }" : "=r"(a) : "l"(p));
    return a;
}
static __device__ __forceinline__ uint64_t gptr(const void* p) {
    uint64_t a;
    asm("cvta.to.global.u64 %0, %1;" : "=l"(a) : "l"(p));
    return a;
}

// ---------------------------------------------------------------------------
// Prep: g_rel (row-major, tf32-rounded GEMM operand) + g_relT (exact weights)
// ---------------------------------------------------------------------------
__global__ void prep_rel_kernel(const float* __restrict__ x,
                                const float* __restrict__ offsets) {
    int idx = blockIdx.x * blockDim.x + threadIdx.x;   // k*BATCH + b
    int k = idx / BATCH;
    int b = idx % BATCH;
    if (k < DIMS) {
        float r = x[b * DIMS + k] - offsets[k];
        g_relT[idx] = r;
        g_rel[b * DIMS + k] = f2tf32f(r);
    } else {
        g_relT[idx] = 1.0f;
    }
}

__global__ void init_out_kernel(const float* __restrict__ c0p,
                                float* __restrict__ out) {
    int b = blockIdx.x * blockDim.x + threadIdx.x;
    if (b < BATCH) out[b] = c0p[0];
}

// ---------------------------------------------------------------------------
// Pack: symmetrize c3 upper triangle (+c2, +c1, +pad), tf32-round once.
// ---------------------------------------------------------------------------
__global__ void pack_kernel(const float* __restrict__ c3,
                            const float* __restrict__ c2,
                            const float* __restrict__ c1) {
    int j = blockIdx.x, i = blockIdx.y, t = threadIdx.x;
    int p;
    float4 v;
    uint32_t pidx;
    if (i < 256) {
        if (j < i) return;
        p = i * 256 - (i * (i - 1)) / 2 + (j - i);
        v = *(const float4*)(c3 + ((size_t)(i * 256 + j)) * DIMS + t * 4);
        if (i != j) {
            float4 w = *(const float4*)(c3 + ((size_t)(j * 256 + i)) * DIMS + t * 4);
            v.x += w.x; v.y += w.y; v.z += w.z; v.w += w.w;
        }
        pidx = ((uint32_t)i << 16) | (uint32_t)j;
    } else if (i == 256) {                       // c2 rows: weight r_j * 1
        p = NPAIR + j;
        v = *(const float4*)(c2 + (size_t)j * DIMS + t * 4);
        pidx = (256u << 16) | (uint32_t)j;
    } else {                                     // i == 257
        if (j == 0) {                            // c1 row: weight 1 * 1
            p = NPAIR + 256;
            v = *(const float4*)(c1 + t * 4);
        } else if (j < 128) {                    // zero pad
            p = NPAIR + 256 + j;
            v = make_float4(0.f, 0.f, 0.f, 0.f);
        } else return;
        pidx = (256u << 16) | 256u;
    }
    v.x = f2tf32f(v.x); v.y = f2tf32f(v.y); v.z = f2tf32f(v.z); v.w = f2tf32f(v.w);
    *(float4*)(g_c3p + (size_t)p * DIMS + t * 4) = v;
    if (t == 0) g_pairIdx[p] = pidx;
}

// ---------------------------------------------------------------------------
// Main fused GEMM: 3-stage cp.async pipeline + ldmatrix fragments.
// ---------------------------------------------------------------------------
#define STAGE_BYTES (2 * BM * KC * 4)            // 32 KB (A 16K + B 16K)
#define SMEM_BYTES  (STAGES * STAGE_BYTES + BN * 4)

__global__ void __launch_bounds__(256, 2) taylor_mma_kernel(
    float* __restrict__ out) {

    extern __shared__ char smem[];
    const uint32_t sb = smem_u32(smem);
    float* sred = (float*)(smem + STAGES * STAGE_BYTES);

    const int tid  = threadIdx.x;
    const int lane = tid & 31, wid = tid >> 5;
    const int warpM = wid & 3, warpN = wid >> 2;
    const int g = lane >> 2, tig = lane & 3;
    const int p0 = blockIdx.x * BM;
    const int b0 = blockIdx.y * BN;

    const uint64_t Ag = gptr(g_c3p) + ((size_t)p0 * DIMS) * 4;
    const uint64_t Bg = gptr(g_rel) + ((size_t)b0 * DIMS) * 4;

    // per-thread cp.async coords (4 segments each for A and B per chunk)
    // idx = tid + it*256 ; row = idx>>3 ; seg = idx&7 (16B segment)
    uint32_t cprow[4], cpdst[4];
#pragma unroll
    for (int it = 0; it < 4; it++) {
        int idx = tid + it * 256;
        int row = idx >> 3, seg = idx & 7;
        cprow[it] = row;
        cpdst[it] = row * 128 + ((seg ^ (row & 7)) << 4);
    }
    auto load_chunk = [&](int c, int stage) {
        const uint32_t sa = sb + stage * STAGE_BYTES;
        const uint32_t sbf = sa + BM * KC * 4;
        const int k0 = c * KC;
#pragma unroll
        for (int it = 0; it < 4; it++) {
            int idx = tid + it * 256;
            int seg = idx & 7;
            uint64_t goff = ((size_t)cprow[it] * DIMS + k0 + seg * 4) * 4;
            cp16(sa  + cpdst[it], Ag + goff);
            cp16(sbf + cpdst[it], Bg + goff);
        }
    };

    // ldmatrix per-thread addresses (byte offsets within a stage)
    const int rowA0 = warpM * 32 + ((lane >> 3) & 1) * 8 + (lane & 7);
    const int rowA1 = rowA0 + 16;
    const int kcA   = (lane >> 4) & 1;
    const int rowB0 = warpN * 64 + ((lane >> 4) & 1) * 8 + (lane & 7);
    const int kcB   = (lane >> 3) & 1;

    float acc[2][8][4];
#pragma unroll
    for (int m = 0; m < 2; m++)
#pragma unroll
        for (int n = 0; n < 8; n++)
#pragma unroll
            for (int r = 0; r < 4; r++) acc[m][n][r] = 0.f;

    if (tid < BN) sred[tid] = 0.f;

    // prologue: fill all 3 stages
    load_chunk(0, 0); CP_COMMIT();
    load_chunk(1, 1); CP_COMMIT();
    load_chunk(2, 2); CP_COMMIT();

    int stage = 0;
    for (int c = 0; c < NCHUNK; ++c) {
        CP_WAIT2();              // chunk c resident (2 younger groups pending)
        __syncthreads();

        const uint32_t As = sb + stage * STAGE_BYTES;
        const uint32_t Bs = As + BM * KC * 4;

#pragma unroll
        for (int ks = 0; ks < KC / 8; ++ks) {
            uint32_t a0[4], a1[4];
            LDSM4(a0, As + rowA0 * 128 + ((((ks << 1) | kcA) ^ (rowA0 & 7)) << 4));
            LDSM4(a1, As + rowA1 * 128 + ((((ks << 1) | kcA) ^ (rowA1 & 7)) << 4));
            uint32_t bb[4][4];
#pragma unroll
            for (int p = 0; p < 4; ++p) {
                int rowB = rowB0 + p * 16;
                LDSM4(bb[p], Bs + rowB * 128 + ((((ks << 1) | kcB) ^ (rowB & 7)) << 4));
            }
#pragma unroll
            for (int p = 0; p < 4; ++p) {
                MMA_TF32(acc[0][2 * p],     a0[0], a0[1], a0[2], a0[3], bb[p][0], bb[p][1]);
                MMA_TF32(acc[0][2 * p + 1], a0[0], a0[1], a0[2], a0[3], bb[p][2], bb[p][3]);
                MMA_TF32(acc[1][2 * p],     a1[0], a1[1], a1[2], a1[3], bb[p][0], bb[p][1]);
                MMA_TF32(acc[1][2 * p + 1], a1[0], a1[1], a1[2], a1[3], bb[p][2], bb[p][3]);
            }
        }

        __syncthreads();         // all warps done reading this stage
        if (c + STAGES < NCHUNK) load_chunk(c + STAGES, stage);
        CP_COMMIT();             // always commit (possibly empty) to keep distance fixed
        stage = (stage + 1 == STAGES) ? 0 : stage + 1;
    }

    // ---- epilogue: sred[col] += sum_m D[m,col] * r_i(m)[b] * r_j(m)[b] ----
    const float* wi[2][2];
    const float* wj[2][2];
#pragma unroll
    for (int msl = 0; msl < 2; ++msl)
#pragma unroll
        for (int h = 0; h < 2; ++h) {
            int rloc = warpM * 32 + msl * 16 + h * 8 + g;
            uint32_t pij = g_pairIdx[p0 + rloc];
            wi[msl][h] = g_relT + (size_t)(pij >> 16) * BATCH + b0;
            wj[msl][h] = g_relT + (size_t)(pij & 0xFFFF) * BATCH + b0;
        }

#pragma unroll
    for (int nsl = 0; nsl < 8; ++nsl) {
        const int coln = warpN * 64 + nsl * 8 + tig * 2;
        float s0 = 0.f, s1 = 0.f;
#pragma unroll
        for (int msl = 0; msl < 2; ++msl) {
            float2 a = *(const float2*)(wi[msl][0] + coln);
            float2 b = *(const float2*)(wj[msl][0] + coln);
            s0 += acc[msl][nsl][0] * a.x * b.x;
            s1 += acc[msl][nsl][1] * a.y * b.y;
            a = *(const float2*)(wi[msl][1] + coln);
            b = *(const float2*)(wj[msl][1] + coln);
            s0 += acc[msl][nsl][2] * a.x * b.x;
            s1 += acc[msl][nsl][3] * a.y * b.y;
        }
#pragma unroll
        for (int o = 4; o <= 16; o <<= 1) {
            s0 += __shfl_xor_sync(0xFFFFFFFFu, s0, o);
            s1 += __shfl_xor_sync(0xFFFFFFFFu, s1, o);
        }
        if (g == 0) {
            atomicAdd(&sred[coln],     s0);
            atomicAdd(&sred[coln + 1], s1);
        }
    }
    __syncthreads();

    if (tid < BN) atomicAdd(out + b0 + tid, sred[tid]);
}

// ---------------------------------------------------------------------------
extern "C" void kernel_launch(void* const* d_in, const int* in_sizes, int n_in,
                              void* d_out, int out_size) {
    const float* x       = (const float*)d_in[0];
    const float* offsets = (const float*)d_in[1];
    const float* coeff0  = (const float*)d_in[2];
    const float* coeff1  = (const float*)d_in[3];
    const float* coeff2  = (const float*)d_in[4];
    const float* coeff3  = (const float*)d_in[5];
    float* out = (float*)d_out;

    cudaFuncSetAttribute(taylor_mma_kernel,
                         cudaFuncAttributeMaxDynamicSharedMemorySize, SMEM_BYTES);

    prep_rel_kernel<<<((DIMS + 1) * BATCH) / 256, 256>>>(x, offsets);
    init_out_kernel<<<BATCH / 256, 256>>>(coeff0, out);

    dim3 pgrid(256, 258);
    pack_kernel<<<pgrid, 64>>>(coeff3, coeff2, coeff1);

    dim3 grid(NROWS / BM, BATCH / BN);   // (260, 16)
    taylor_mma_kernel<<<grid, 256, SMEM_BYTES>>>(out);
}

// round 6
// speedup vs baseline: 1.1512x; 1.1512x over previous
#include <cuda_runtime.h>
#include <cstdint>

#define DIMS   256
#define BATCH  2048
#define NPAIR  32896              // 256*257/2 upper-triangle pairs
#define NROWS  33280              // 260 tiles * 128 rows (pairs + c2 + c1 + pad)
#define BM     128
#define BN     128
#define KC     32
#define NCHUNK (DIMS / KC)        // 8
#define STAGES 3

// ---- device scratch (allocation-free) ----
__device__ float    g_c3p[NROWS * DIMS];         // 34 MB packed A, tf32-pre-rounded
__device__ uint32_t g_pairIdx[NROWS];            // (i<<16)|j per row
__device__ float    g_rel[BATCH * DIMS];         // rel row-major, tf32-pre-rounded
__device__ float    g_relT[(DIMS + 1) * BATCH];  // rel^T exact; row 256 = 1.0

static __device__ __forceinline__ float f2tf32f(float f) {
    uint32_t r;
    asm("cvt.rna.tf32.f32 %0, %1;" : "=r"(r) : "f"(f));
    return __uint_as_float(r);
}

#define MMA_TF32(C, A0, A1, A2, A3, B0, B1)                                   \
    asm volatile(                                                             \
        "mma.sync.aligned.m16n8k8.row.col.f32.tf32.tf32.f32 "                 \
        "{%0,%1,%2,%3}, {%4,%5,%6,%7}, {%8,%9}, {%0,%1,%2,%3};"               \
        : "+f"((C)[0]), "+f"((C)[1]), "+f"((C)[2]), "+f"((C)[3])              \
        : "r"(A0), "r"(A1), "r"(A2), "r"(A3), "r"(B0), "r"(B1))

#define LDSM4(R, addr)                                                        \
    asm volatile("ldmatrix.sync.aligned.m8n8.x4.shared.b16 {%0,%1,%2,%3}, [%4];" \
        : "=r"((R)[0]), "=r"((R)[1]), "=r"((R)[2]), "=r"((R)[3])              \
        : "r"(addr))

static __device__ __forceinline__ uint32_t smem_u32(const void* p) {
    uint32_t a;
    asm("{ .reg .u64 t; cvta.to.shared.u64 t, %1; cvt.u32.u64 %0, t; }" : "=r"(a) : "l"(p));
    return a;
}

// ---------------------------------------------------------------------------
__global__ void prep_rel_kernel(const float* __restrict__ x,
                                const float* __restrict__ offsets) {
    int idx = blockIdx.x * blockDim.x + threadIdx.x;   // k*BATCH + b
    int k = idx / BATCH;
    int b = idx % BATCH;
    if (k < DIMS) {
        float r = x[b * DIMS + k] - offsets[k];
        g_relT[idx] = r;
        g_rel[b * DIMS + k] = f2tf32f(r);
    } else {
        g_relT[idx] = 1.0f;
    }
}

__global__ void init_out_kernel(const float* __restrict__ c0p,
                                float* __restrict__ out) {
    int b = blockIdx.x * blockDim.x + threadIdx.x;
    if (b < BATCH) out[b] = c0p[0];
}

// ---------------------------------------------------------------------------
// Pack: symmetrize c3 upper triangle (+c2, +c1, +pad), tf32-round once.
// ---------------------------------------------------------------------------
__global__ void pack_kernel(const float* __restrict__ c3,
                            const float* __restrict__ c2,
                            const float* __restrict__ c1) {
    int j = blockIdx.x, i = blockIdx.y, t = threadIdx.x;
    int p;
    float4 v;
    uint32_t pidx;
    if (i < 256) {
        if (j < i) return;
        p = i * 256 - (i * (i - 1)) / 2 + (j - i);
        v = *(const float4*)(c3 + ((size_t)(i * 256 + j)) * DIMS + t * 4);
        if (i != j) {
            float4 w = *(const float4*)(c3 + ((size_t)(j * 256 + i)) * DIMS + t * 4);
            v.x += w.x; v.y += w.y; v.z += w.z; v.w += w.w;
        }
        pidx = ((uint32_t)i << 16) | (uint32_t)j;
    } else if (i == 256) {                       // c2 rows: weight r_j * 1
        p = NPAIR + j;
        v = *(const float4*)(c2 + (size_t)j * DIMS + t * 4);
        pidx = (256u << 16) | (uint32_t)j;
    } else {                                     // i == 257
        if (j == 0) {                            // c1 row: weight 1 * 1
            p = NPAIR + 256;
            v = *(const float4*)(c1 + t * 4);
        } else if (j < 128) {                    // zero pad
            p = NPAIR + 256 + j;
            v = make_float4(0.f, 0.f, 0.f, 0.f);
        } else return;
        pidx = (256u << 16) | 256u;
    }
    v.x = f2tf32f(v.x); v.y = f2tf32f(v.y); v.z = f2tf32f(v.z); v.w = f2tf32f(v.w);
    *(float4*)(g_c3p + (size_t)p * DIMS + t * 4) = v;
    if (t == 0) g_pairIdx[p] = pidx;
}

// ---------------------------------------------------------------------------
// Main fused GEMM: LDG->reg->STS staging (3 rotating buffers, 1 sync/chunk),
// ldmatrix fragment loads, mma.sync tf32, fused weighted reduction.
// ---------------------------------------------------------------------------
#define STAGE_BYTES (2 * BM * KC * 4)            // 32 KB (A 16K + B 16K)
#define SMEM_BYTES  (STAGES * STAGE_BYTES + BN * 4)

__global__ void __launch_bounds__(256, 2) taylor_mma_kernel(
    float* __restrict__ out) {

    extern __shared__ char smem[];
    const uint32_t sb = smem_u32(smem);
    float* sred = (float*)(smem + STAGES * STAGE_BYTES);

    const int tid  = threadIdx.x;
    const int lane = tid & 31, wid = tid >> 5;
    const int warpM = wid & 3, warpN = wid >> 2;
    const int g = lane >> 2, tig = lane & 3;
    const int p0 = blockIdx.x * BM;
    const int b0 = blockIdx.y * BN;

    const float* Ag = g_c3p + (size_t)p0 * DIMS;
    const float* Bg = g_rel + (size_t)b0 * DIMS;

    // staging coords: idx = tid + it*256; row = idx>>3; seg = idx&7 (16B)
    uint32_t stsoff[4];
#pragma unroll
    for (int it = 0; it < 4; it++) {
        int idx = tid + it * 256;
        int row = idx >> 3, seg = idx & 7;
        stsoff[it] = row * 128 + ((seg ^ (row & 7)) << 4);
    }

    float4 pa[4], pb[4];
    auto ldg_chunk = [&](int c) {
        const int k0 = c * KC;
#pragma unroll
        for (int it = 0; it < 4; it++) {
            int idx = tid + it * 256;
            int row = idx >> 3, kk = (idx & 7) << 2;
            pa[it] = *(const float4*)(Ag + (size_t)row * DIMS + k0 + kk);
            pb[it] = *(const float4*)(Bg + (size_t)row * DIMS + k0 + kk);
        }
    };
    auto sts_chunk = [&](int stage) {
        char* As = smem + stage * STAGE_BYTES;
        char* Bs = As + BM * KC * 4;
#pragma unroll
        for (int it = 0; it < 4; it++) {
            *(float4*)(As + stsoff[it]) = pa[it];
            *(float4*)(Bs + stsoff[it]) = pb[it];
        }
    };

    // ldmatrix per-thread addressing (validated in round 5; same swizzle)
    const int rowA0 = warpM * 32 + ((lane >> 3) & 1) * 8 + (lane & 7);
    const int rowA1 = rowA0 + 16;
    const int kcA   = (lane >> 4) & 1;
    const int rowB0 = warpN * 64 + ((lane >> 4) & 1) * 8 + (lane & 7);
    const int kcB   = (lane >> 3) & 1;

    float acc[2][8][4];
#pragma unroll
    for (int m = 0; m < 2; m++)
#pragma unroll
        for (int n = 0; n < 8; n++)
#pragma unroll
            for (int r = 0; r < 4; r++) acc[m][n][r] = 0.f;

    if (tid < BN) sred[tid] = 0.f;

    // prologue: chunk0 -> buf0; chunk1 -> regs
    ldg_chunk(0);
    sts_chunk(0);
    ldg_chunk(1);
    __syncthreads();

    for (int c = 0; c < NCHUNK; ++c) {
        // regs hold chunk c+1: stage it into buf (c+1)%3
        if (c + 1 < NCHUNK) sts_chunk((c + 1) % STAGES);
        // deep prefetch chunk c+2
        if (c + 2 < NCHUNK) ldg_chunk(c + 2);

        const uint32_t As = sb + (c % STAGES) * STAGE_BYTES;
        const uint32_t Bs = As + BM * KC * 4;
#pragma unroll
        for (int ks = 0; ks < KC / 8; ++ks) {
            uint32_t a0[4], a1[4];
            LDSM4(a0, As + rowA0 * 128 + ((((ks << 1) | kcA) ^ (rowA0 & 7)) << 4));
            LDSM4(a1, As + rowA1 * 128 + ((((ks << 1) | kcA) ^ (rowA1 & 7)) << 4));
            uint32_t bb[4][4];
#pragma unroll
            for (int p = 0; p < 4; ++p) {
                int rowB = rowB0 + p * 16;
                LDSM4(bb[p], Bs + rowB * 128 + ((((ks << 1) | kcB) ^ (rowB & 7)) << 4));
            }
#pragma unroll
            for (int p = 0; p < 4; ++p) {
                MMA_TF32(acc[0][2 * p],     a0[0], a0[1], a0[2], a0[3], bb[p][0], bb[p][1]);
                MMA_TF32(acc[0][2 * p + 1], a0[0], a0[1], a0[2], a0[3], bb[p][2], bb[p][3]);
                MMA_TF32(acc[1][2 * p],     a1[0], a1[1], a1[2], a1[3], bb[p][0], bb[p][1]);
                MMA_TF32(acc[1][2 * p + 1], a1[0], a1[1], a1[2], a1[3], bb[p][2], bb[p][3]);
            }
        }
        __syncthreads();   // single barrier per chunk
    }

    // ---- epilogue: sred[col] += sum_m D[m,col] * r_i(m)[b] * r_j(m)[b] ----
    const float* wi[2][2];
    const float* wj[2][2];
#pragma unroll
    for (int msl = 0; msl < 2; ++msl)
#pragma unroll
        for (int h = 0; h < 2; ++h) {
            int rloc = warpM * 32 + msl * 16 + h * 8 + g;
            uint32_t pij = g_pairIdx[p0 + rloc];
            wi[msl][h] = g_relT + (size_t)(pij >> 16) * BATCH + b0;
            wj[msl][h] = g_relT + (size_t)(pij & 0xFFFF) * BATCH + b0;
        }

#pragma unroll
    for (int nsl = 0; nsl < 8; ++nsl) {
        const int coln = warpN * 64 + nsl * 8 + tig * 2;
        float s0 = 0.f, s1 = 0.f;
#pragma unroll
        for (int msl = 0; msl < 2; ++msl) {
            float2 a = *(const float2*)(wi[msl][0] + coln);
            float2 b = *(const float2*)(wj[msl][0] + coln);
            s0 += acc[msl][nsl][0] * a.x * b.x;
            s1 += acc[msl][nsl][1] * a.y * b.y;
            a = *(const float2*)(wi[msl][1] + coln);
            b = *(const float2*)(wj[msl][1] + coln);
            s0 += acc[msl][nsl][2] * a.x * b.x;
            s1 += acc[msl][nsl][3] * a.y * b.y;
        }
#pragma unroll
        for (int o = 4; o <= 16; o <<= 1) {
            s0 += __shfl_xor_sync(0xFFFFFFFFu, s0, o);
            s1 += __shfl_xor_sync(0xFFFFFFFFu, s1, o);
        }
        if (g == 0) {
            atomicAdd(&sred[coln],     s0);
            atomicAdd(&sred[coln + 1], s1);
        }
    }
    __syncthreads();

    if (tid < BN) atomicAdd(out + b0 + tid, sred[tid]);
}

// ---------------------------------------------------------------------------
extern "C" void kernel_launch(void* const* d_in, const int* in_sizes, int n_in,
                              void* d_out, int out_size) {
    const float* x       = (const float*)d_in[0];
    const float* offsets = (const float*)d_in[1];
    const float* coeff0  = (const float*)d_in[2];
    const float* coeff1  = (const float*)d_in[3];
    const float* coeff2  = (const float*)d_in[4];
    const float* coeff3  = (const float*)d_in[5];
    float* out = (float*)d_out;

    cudaFuncSetAttribute(taylor_mma_kernel,
                         cudaFuncAttributeMaxDynamicSharedMemorySize, SMEM_BYTES);

    prep_rel_kernel<<<((DIMS + 1) * BATCH) / 256, 256>>>(x, offsets);
    init_out_kernel<<<BATCH / 256, 256>>>(coeff0, out);

    dim3 pgrid(256, 258);
    pack_kernel<<<pgrid, 64>>>(coeff3, coeff2, coeff1);

    dim3 grid(NROWS / BM, BATCH / BN);   // (260, 16)
    taylor_mma_kernel<<<grid, 256, SMEM_BYTES>>>(out);
}